// round 17
// baseline (speedup 1.0000x reference)
#include <cuda_runtime.h>
#include <cuda.h>
#include <cuda_bf16.h>
#include <math.h>
#include <stdint.h>

#define D_MODEL 4096
#define D_IN1   4112
#define D_CTRL  64
#define BATCH   4
#define SEQ     2048
#define BS_TOT  8192

// ---------------- GEMM tiling (TMA-A champion) ----------------
#define MTILE    128
#define KSPLIT   4
#define KPER     (D_MODEL / KSPLIT)     // 1024
#define KC       32                     // k elems per chunk (128 B row)
#define NCHUNK   (KPER / KC)            // 32
#define NSTG     4
#define ASTG     16384                  // 128 rows x 128 B (SW128 tile)
#define BROWH    40                     // B row stride (bf16)
#define BSTG     (D_CTRL * BROWH * 2)   // 5120 B
#define BOFF     (NSTG * ASTG)          // 65536
#define MOFF     (BOFF + NSTG * BSTG)   // 86016
#define SMEM_DYN (MOFF + 64 + 1024)     // + mbars + align slack

__device__ __align__(16) __nv_bfloat16 g_weff[D_CTRL * D_MODEL];   // 512 KiB
__device__ __align__(16) float g_partial[BS_TOT * KSPLIT * D_CTRL]; // 8 MiB
__device__ __align__(16) float g_delta[BS_TOT];
__device__ __align__(16) float g_carry[64];
__device__ __align__(128) unsigned char g_tmapA[128];

// ---------------- helpers ----------------
__device__ __forceinline__ uint32_t smem_u32(const void* p) {
    uint32_t a;
    asm("{ .reg .u64 t; cvta.to.shared.u64 t, %1; cvt.u32.u64 %0, t; }" : "=r"(a) : "l"(p));
    return a;
}
__device__ __forceinline__ void cp16(uint32_t dst, const void* src) {
    asm volatile("cp.async.cg.shared.global [%0], [%1], 16;" :: "r"(dst), "l"(src));
}
__device__ __forceinline__ uint32_t pack_bf16(float hi, float lo) {
    uint32_t r;
    asm("cvt.rn.bf16x2.f32 %0, %1, %2;" : "=r"(r) : "f"(hi), "f"(lo));
    return r;
}
__device__ __forceinline__ float2 lds64(uint32_t addr) {
    float2 v;
    asm volatile("ld.shared.v2.f32 {%0,%1}, [%2];" : "=f"(v.x), "=f"(v.y) : "r"(addr));
    return v;
}
__device__ __forceinline__ void mma_bf16(float* d, const uint32_t* a, const uint32_t* b) {
    asm volatile(
        "mma.sync.aligned.m16n8k16.row.col.f32.bf16.bf16.f32 "
        "{%0,%1,%2,%3}, {%4,%5,%6,%7}, {%8,%9}, {%0,%1,%2,%3};"
        : "+f"(d[0]), "+f"(d[1]), "+f"(d[2]), "+f"(d[3])
        : "r"(a[0]), "r"(a[1]), "r"(a[2]), "r"(a[3]), "r"(b[0]), "r"(b[1]));
}
__device__ __forceinline__ void mbar_init(uint32_t mb, uint32_t cnt) {
    asm volatile("mbarrier.init.shared.b64 [%0], %1;" :: "r"(mb), "r"(cnt) : "memory");
}
__device__ __forceinline__ void mbar_expect_tx(uint32_t mb, uint32_t bytes) {
    asm volatile("mbarrier.arrive.expect_tx.shared.b64 _, [%0], %1;"
                 :: "r"(mb), "r"(bytes) : "memory");
}
__device__ __forceinline__ void mbar_wait(uint32_t mb, uint32_t parity) {
    uint32_t done;
    asm volatile(
        "{\n\t.reg .pred p;\n\t"
        "mbarrier.try_wait.parity.acquire.cta.shared::cta.b64 p, [%1], %2;\n\t"
        "selp.b32 %0, 1, 0, p;\n\t}"
        : "=r"(done) : "r"(mb), "r"(parity) : "memory");
    if (!done) {
        asm volatile(
            "{\n\t.reg .pred P1;\n\t"
            "WL_%=:\n\t"
            "mbarrier.try_wait.parity.acquire.cta.shared::cta.b64 P1, [%0], %1, 0x989680;\n\t"
            "@P1 bra.uni WD_%=;\n\t"
            "bra.uni WL_%=;\n\t"
            "WD_%=:\n\t}"
            :: "r"(mb), "r"(parity) : "memory");
    }
}
__device__ __forceinline__ void tma2d(uint32_t smem, const void* tmap,
                                      int x, int y, uint32_t mbar) {
    asm volatile(
        "cp.async.bulk.tensor.2d.shared::cta.global.tile.mbarrier::complete_tx::bytes "
        "[%0], [%1, {%2, %3}], [%4];"
        :: "r"(smem), "l"(tmap), "r"(x), "r"(y), "r"(mbar) : "memory");
}
__device__ __forceinline__ float gelu_exact(float x) {
    return 0.5f * x * (1.0f + erff(x * 0.7071067811865476f));
}
__device__ __forceinline__ float softplus_f(float x) {
    return fmaxf(x, 0.0f) + log1pf(expf(-fabsf(x)));
}

// ============================================================
// Kernel 1: Weff (bf16) = W1[:, :4096] + W1[:, 4096:] @ W_fiber
// ============================================================
__global__ void weff_kernel(const float* __restrict__ W1,
                            const float* __restrict__ Wf) {
    __shared__ float tail[16];
    const int k = blockIdx.y;
    if (threadIdx.x < 16) tail[threadIdx.x] = W1[(size_t)k * D_IN1 + D_MODEL + threadIdx.x];
    __syncthreads();
    const int d4 = blockIdx.x * 256 + threadIdx.x;
    float4 v = *(const float4*)&W1[(size_t)k * D_IN1 + d4 * 4];
#pragma unroll
    for (int f = 0; f < 16; ++f) {
        float4 wf = *(const float4*)&Wf[(size_t)f * D_MODEL + d4 * 4];
        float t = tail[f];
        v.x = fmaf(t, wf.x, v.x);
        v.y = fmaf(t, wf.y, v.y);
        v.z = fmaf(t, wf.z, v.z);
        v.w = fmaf(t, wf.w, v.w);
    }
    uint2 pk;
    pk.x = pack_bf16(v.y, v.x);
    pk.y = pack_bf16(v.w, v.z);
    *(uint2*)&g_weff[(size_t)k * D_MODEL + d4 * 4] = pk;
}

// ============================================================
// Kernel 2: split-K bf16 mma GEMM, A via TMA (1 load/stage) -> g_partial
// grid (64, 4), 512 threads (16 warps), warp = 16 rows x 32 cols, 2 CTAs/SM
// ============================================================
__global__ void __launch_bounds__(512, 2)
gemm_mma_kernel(const float* __restrict__ hidden) {
    extern __shared__ char smc[];
    const uint32_t sb0 = smem_u32(smc);
    const uint32_t sbA = (sb0 + 1023u) & ~1023u;
    const uint32_t sbB = sbA + BOFF;
    const uint32_t sbM = sbA + MOFF;

    const int tid  = threadIdx.x;
    const int lane = tid & 31;
    const int w    = tid >> 5;
    const int g    = lane >> 2;
    const int tig  = lane & 3;
    const int rowgrp = w >> 1;          // 0..7
    const int colh   = w & 1;           // 0..1
    const int rowbase = blockIdx.x * MTILE;
    const int ks      = blockIdx.y;
    const int kbase   = ks * KPER;

    if (tid == 0) {
#pragma unroll
        for (int s = 0; s < NSTG; ++s) mbar_init(sbM + s * 8, 1);
    }
    __syncthreads();

    float acc[4][4];
#pragma unroll
    for (int n = 0; n < 4; ++n)
#pragma unroll
        for (int j = 0; j < 4; ++j) acc[n][j] = 0.0f;

    // B producer: threads 0..255, one cp16/stage
    const int brow = tid >> 2;
    const int bunit = tid & 3;
    const __nv_bfloat16* gB = g_weff + (size_t)brow * D_MODEL + kbase + bunit * 8;
    const uint32_t bDst0 = sbB + (uint32_t)(brow * BROWH + bunit * 8) * 2;
    const bool doB = (tid < 256);

    // B consumer ldmatrix lane base
    const uint32_t lmAddr0 = sbB
        + (uint32_t)((colh * 32 + (lane & 7)) * (BROWH * 2) + (lane >> 3) * 16);

    // A consumer swizzled bases: rows rowgrp*16+g and +8, xor term g<<4
    const uint32_t aRow0 = (uint32_t)(rowgrp * 16 + g) * 128;
    const int xo = g << 4;

    // ---- prologue: fill all NSTG stages (chunks 0..3) ----
#pragma unroll
    for (int s = 0; s < NSTG; ++s) {
        if (tid == 0) {
            mbar_expect_tx(sbM + s * 8, (uint32_t)ASTG);
            tma2d(sbA + s * ASTG, (const void*)g_tmapA,
                  kbase + s * KC, rowbase, sbM + s * 8);
        }
        if (doB) cp16(bDst0 + s * BSTG, gB + s * KC);
        asm volatile("cp.async.commit_group;" ::: "memory");
    }

    for (int c = 0; c < NCHUNK; ++c) {
        const int s = c & (NSTG - 1);
        asm volatile("cp.async.wait_group %0;" :: "n"(NSTG - 1) : "memory");
        mbar_wait(sbM + s * 8, (uint32_t)((c >> 2) & 1));
        __syncthreads();

        // B fragments: 4 ldmatrix.x4 per warp
        uint32_t bq[4][4];
        {
            const uint32_t lmS = lmAddr0 + s * BSTG;
#pragma unroll
            for (int n = 0; n < 4; ++n) {
                asm volatile(
                    "ldmatrix.sync.aligned.m8n8.x4.shared.b16 {%0,%1,%2,%3}, [%4];"
                    : "=r"(bq[n][0]), "=r"(bq[n][1]), "=r"(bq[n][2]), "=r"(bq[n][3])
                    : "r"(lmS + n * (8 * BROWH * 2)));
            }
        }

        // A fragments from SW128-swizzled TMA tile
        const uint32_t aS = sbA + s * ASTG + aRow0;
#pragma unroll
        for (int kk = 0; kk < 2; ++kk) {
            const int colk = kk * 64 + tig * 8;
            const uint32_t c0 = (uint32_t)(colk ^ xo);
            const uint32_t c1 = (uint32_t)((colk + 32) ^ xo);
            float2 p0 = lds64(aS + c0);
            float2 p1 = lds64(aS + c1);
            float2 p2 = lds64(aS + 8 * 128 + c0);
            float2 p3 = lds64(aS + 8 * 128 + c1);
            uint32_t a[4];
            a[0] = pack_bf16(p0.y, p0.x);
            a[1] = pack_bf16(p2.y, p2.x);
            a[2] = pack_bf16(p1.y, p1.x);
            a[3] = pack_bf16(p3.y, p3.x);
#pragma unroll
            for (int n = 0; n < 4; ++n)
                mma_bf16(acc[n], a, &bq[n][2 * kk]);
        }
        __syncthreads();

        // refill slot s with chunk c+NSTG
        const int cn = c + NSTG;
        if (cn < NCHUNK) {
            if (tid == 0) {
                mbar_expect_tx(sbM + s * 8, (uint32_t)ASTG);
                tma2d(sbA + s * ASTG, (const void*)g_tmapA,
                      kbase + cn * KC, rowbase, sbM + s * 8);
            }
            if (doB) cp16(bDst0 + s * BSTG, gB + cn * KC);
        }
        asm volatile("cp.async.commit_group;" ::: "memory");
    }

    // write partials: [row][ks][col]
    const int row0 = rowbase + rowgrp * 16 + g;
#pragma unroll
    for (int n = 0; n < 4; ++n) {
        const int col = colh * 32 + 8 * n + 2 * tig;
        *(float2*)&g_partial[((size_t)row0 * 4 + ks) * 64 + col] =
            make_float2(acc[n][0], acc[n][1]);
        *(float2*)&g_partial[((size_t)(row0 + 8) * 4 + ks) * 64 + col] =
            make_float2(acc[n][2], acc[n][3]);
    }
}

// ============================================================
// Kernel 3: reduce split-K partials + GELU dot W2 + softplus -> g_delta
// ============================================================
__global__ void __launch_bounds__(256)
reduce_kernel(const float* __restrict__ b1,
              const float* __restrict__ W2,
              const float* __restrict__ b2) {
    const int w = threadIdx.x >> 5, lane = threadIdx.x & 31;
    const int row = blockIdx.x * 8 + w;
    const int col = 2 * lane;

    float2 s = make_float2(0.0f, 0.0f);
#pragma unroll
    for (int ks = 0; ks < KSPLIT; ++ks) {
        float2 p = *(const float2*)&g_partial[((size_t)row * 4 + ks) * 64 + col];
        s.x += p.x;
        s.y += p.y;
    }
    float v = gelu_exact(s.x + b1[col]) * W2[col]
            + gelu_exact(s.y + b1[col + 1]) * W2[col + 1];
#pragma unroll
    for (int off = 16; off > 0; off >>= 1)
        v += __shfl_xor_sync(0xffffffffu, v, off);
    if (lane == 0) g_delta[row] = softplus_f(v + b2[0]);
}

// ============================================================
// Kernel 4: EMA carries + mean via hierarchical affine scan
// ============================================================
__global__ void __launch_bounds__(512)
ema_carry_kernel(float* __restrict__ out) {
    __shared__ float wtot[16], wsum[16], warpH[16];
    const int tid = threadIdx.x;
    const int warp = tid >> 5, lane = tid & 31;
    const float alpha = 0.9f, onem = 0.1f;
    const float A16  = 0.18530201888518416f;
    const float A512 = 3.7339077e-24f;

    float d[16];
    const float4* dv = (const float4*)(g_delta + tid * 16);
#pragma unroll
    for (int q = 0; q < 4; ++q) {
        float4 x = dv[q];
        d[4 * q + 0] = x.x; d[4 * q + 1] = x.y; d[4 * q + 2] = x.z; d[4 * q + 3] = x.w;
    }

    float s = 0.0f, sum = 0.0f;
#pragma unroll
    for (int j = 0; j < 16; ++j) { s = fmaf(alpha, s, onem * d[j]); sum += d[j]; }
#pragma unroll
    for (int off = 16; off > 0; off >>= 1) sum += __shfl_xor_sync(0xffffffffu, sum, off);
    if (lane == 0) wsum[warp] = sum;

    float t = s, Ak = A16;
#pragma unroll
    for (int off = 1; off < 32; off <<= 1) {
        float v = __shfl_up_sync(0xffffffffu, t, off);
        if (lane >= off) t = fmaf(Ak, v, t);
        Ak *= Ak;
    }
    if (lane == 31) wtot[warp] = t;
    __syncthreads();

    if (tid < 4) {
        float carry = 0.0f;
#pragma unroll
        for (int j = 0; j < 4; ++j) {
            warpH[tid * 4 + j] = carry;
            carry = fmaf(A512, carry, wtot[tid * 4 + j]);
        }
    }
    if (tid == 0) {
        float tot = 0.0f;
#pragma unroll
        for (int j = 0; j < 16; ++j) tot += wsum[j];
        out[2 * BS_TOT] = tot * (1.0f / (float)BS_TOT);
    }
    __syncthreads();

    const float texcl = __shfl_up_sync(0xffffffffu, t, 1);
    const float h_ex = fmaf(warpH[warp], __powf(A16, (float)lane),
                            (lane > 0) ? texcl : 0.0f);
    if ((tid & 7) == 0) g_carry[tid >> 3] = h_ex;
}

// ============================================================
// Kernel 5: EMA apply + gate. grid 16 x 128; warp = 128-elem segment
// ============================================================
__global__ void __launch_bounds__(128)
ema_apply_kernel(const float* __restrict__ lam_p, float* __restrict__ out) {
    const int warp = threadIdx.x >> 5, lane = threadIdx.x & 31;
    const int seg = blockIdx.x * 4 + warp;
    const int base = seg * 128 + lane * 4;
    const float alpha = 0.9f, onem = 0.1f;
    const float A4 = 0.6561f;

    float4 x = *(const float4*)(g_delta + base);
    float d[4] = {x.x, x.y, x.z, x.w};

    float s = 0.0f;
#pragma unroll
    for (int j = 0; j < 4; ++j) s = fmaf(alpha, s, onem * d[j]);

    float t = s, Ak = A4;
#pragma unroll
    for (int off = 1; off < 32; off <<= 1) {
        float v = __shfl_up_sync(0xffffffffu, t, off);
        if (lane >= off) t = fmaf(Ak, v, t);
        Ak *= Ak;
    }
    const float texcl = __shfl_up_sync(0xffffffffu, t, 1);
    const float H = g_carry[seg];
    float h = fmaf(H, __powf(A4, (float)lane), (lane > 0) ? texcl : 0.0f);

    const float lam = lam_p[0];
    float fb[4], gb[4];
#pragma unroll
    for (int j = 0; j < 4; ++j) {
        h = fmaf(alpha, h, onem * d[j]);
        fb[j] = h;
        gb[j] = __fdividef(1.0f, 1.0f + __expf(lam * h));
    }
    *(float4*)(out + base)          = make_float4(gb[0], gb[1], gb[2], gb[3]);
    *(float4*)(out + BS_TOT + base) = make_float4(fb[0], fb[1], fb[2], fb[3]);
}

// ============================================================
extern "C" void kernel_launch(void* const* d_in, const int* in_sizes, int n_in,
                              void* d_out, int out_size) {
    const float* hidden = (const float*)d_in[0];
    const float* Wf     = (const float*)d_in[1];
    const float* W1     = (const float*)d_in[2];
    const float* b1     = (const float*)d_in[3];
    const float* W2     = (const float*)d_in[4];
    const float* b2     = (const float*)d_in[5];
    const float* lam    = (const float*)d_in[6];
    float* out = (float*)d_out;

    typedef CUresult (*TMEncode)(
        CUtensorMap*, CUtensorMapDataType, cuuint32_t, void*,
        const cuuint64_t*, const cuuint64_t*, const cuuint32_t*, const cuuint32_t*,
        CUtensorMapInterleave, CUtensorMapSwizzle, CUtensorMapL2promotion,
        CUtensorMapFloatOOBfill);
    static TMEncode enc = nullptr;
    static int inited = 0;
    if (!inited) {
        cudaFuncSetAttribute(gemm_mma_kernel,
                             cudaFuncAttributeMaxDynamicSharedMemorySize, SMEM_DYN);
        void* fp = nullptr;
        cudaDriverEntryPointQueryResult qr;
        cudaGetDriverEntryPoint("cuTensorMapEncodeTiled", &fp,
                                cudaEnableDefault, &qr);
        enc = (TMEncode)fp;
        inited = 1;
    }

    // Encode the A tensormap (same values every call -> deterministic).
    static CUtensorMap h_tmap;
    {
        cuuint64_t dims[2] = {(cuuint64_t)D_MODEL, (cuuint64_t)BS_TOT};
        cuuint64_t str[1]  = {(cuuint64_t)D_MODEL * sizeof(float)};
        cuuint32_t box[2]  = {(cuuint32_t)KC, (cuuint32_t)MTILE};
        cuuint32_t est[2]  = {1, 1};
        enc(&h_tmap, CU_TENSOR_MAP_DATA_TYPE_FLOAT32, 2, (void*)hidden,
            dims, str, box, est, CU_TENSOR_MAP_INTERLEAVE_NONE,
            CU_TENSOR_MAP_SWIZZLE_128B, CU_TENSOR_MAP_L2_PROMOTION_L2_128B,
            CU_TENSOR_MAP_FLOAT_OOB_FILL_NONE);
    }
    cudaMemcpyToSymbolAsync(g_tmapA, &h_tmap, sizeof(CUtensorMap), 0,
                            cudaMemcpyHostToDevice, 0);

    weff_kernel<<<dim3(4, D_CTRL), 256>>>(W1, Wf);
    gemm_mma_kernel<<<dim3(BS_TOT / MTILE, KSPLIT), 512, SMEM_DYN>>>(hidden);
    reduce_kernel<<<BS_TOT / 8, 256>>>(b1, W2, b2);
    ema_carry_kernel<<<1, 512>>>(out);
    ema_apply_kernel<<<16, 128>>>(lam, out);
}